// round 5
// baseline (speedup 1.0000x reference)
#include <cuda_runtime.h>

#define HH   512
#define WW   512
#define HWSZ (HH * WW)
#define CIN  32
#define COUT 24
#define NP   8

typedef unsigned long long u64;

// ---- B300 packed-f32 helpers (PTX f32x2 ops -> FFMA2 in SASS) ----
__device__ __forceinline__ u64 fma2_(u64 a, u64 b, u64 c) {
    u64 d; asm("fma.rn.f32x2 %0, %1, %2, %3;" : "=l"(d) : "l"(a), "l"(b), "l"(c)); return d;
}
__device__ __forceinline__ u64 add2_(u64 a, u64 b) {
    u64 d; asm("add.rn.f32x2 %0, %1, %2;" : "=l"(d) : "l"(a), "l"(b)); return d;
}
__device__ __forceinline__ u64 mul2_(u64 a, u64 b) {
    u64 d; asm("mul.rn.f32x2 %0, %1, %2;" : "=l"(d) : "l"(a), "l"(b)); return d;
}
__device__ __forceinline__ u64 pack2_(float lo, float hi) {
    u64 r; asm("mov.b64 %0, {%1, %2};" : "=l"(r) : "f"(lo), "f"(hi)); return r;
}
__device__ __forceinline__ float2 unpack2_(u64 v) {
    float lo, hi; asm("mov.b64 {%0, %1}, %2;" : "=f"(lo), "=f"(hi) : "l"(v));
    return make_float2(lo, hi);
}

// FUSED single pass (R1 structure: per-dy weight compute + 24-ch accumulate,
// 24 independent FMA chains, channel loads independent of weight math) with
// R4's register economy (raw weights, normalize at store, branch-free masks)
// so it fits 168 regs -> 3 CTAs/SM (12 warps) instead of R1's 255/2-CTA.
__global__ void __launch_bounds__(128, 3) bilat_kernel(
    const float* __restrict__ inp, const float* __restrict__ par,
    float* __restrict__ out)
{
    const int lane = threadIdx.x & 31;
    const int ty   = threadIdx.x >> 5;
    const int x0   = blockIdx.x * 128 + lane * 4;
    const int y    = blockIdx.y * 4 + ty;
    const int b    = blockIdx.z;

    const float* __restrict__ parb = par + b * (NP * HWSZ);
    const float* __restrict__ inpb = inp + b * (CIN * HWSZ);
    float* __restrict__ outb = out + b * (COUT * HWSZ);

    const int xa = max(x0 - 4, 0);          // clamped left col (16B aligned)
    const int xb = x0;
    const int xc = min(x0 + 4, WW - 4);     // clamped right col

    const int cbase = y * WW + x0;
    const u64 M1 = 0xBF800000BF800000ull;   // (-1.0f, -1.0f)

    // x-direction OOB masks (branch-free, computed once)
    u64 mX[5][2];
#pragma unroll
    for (int dx = 0; dx < 5; ++dx) {
        const int g = x0 + dx * 2 - 4;      // global x of tap for pixel 0
        mX[dx][0] = pack2_(((unsigned)(g + 0) < (unsigned)WW) ? 1.0f : 0.0f,
                           ((unsigned)(g + 1) < (unsigned)WW) ? 1.0f : 0.0f);
        mX[dx][1] = pack2_(((unsigned)(g + 2) < (unsigned)WW) ? 1.0f : 0.0f,
                           ((unsigned)(g + 3) < (unsigned)WW) ? 1.0f : 0.0f);
    }

    u64 acc[COUT][2];
#pragma unroll
    for (int c = 0; c < COUT; ++c) { acc[c][0] = 0ull; acc[c][1] = 0ull; }
    u64 ws0 = 0ull, ws1 = 0ull;

#pragma unroll 1
    for (int dy = 0; dy < 5; ++dy) {
        const int   ny = y + dy * 2 - 4;
        const float mr = ((unsigned)ny < (unsigned)HH) ? 1.0f : 0.0f;
        const int   ro = min(max(ny, 0), HH - 1) * WW;

        // ---- squared param distances: flat 32-load block ----
        u64 d2[5][2];
#pragma unroll
        for (int dx = 0; dx < 5; ++dx) { d2[dx][0] = 0ull; d2[dx][1] = 0ull; }

#pragma unroll
        for (int p = 0; p < NP; ++p) {
            const float* pr = parb + p * HWSZ;
            ulonglong2 cc = __ldg(reinterpret_cast<const ulonglong2*>(pr + cbase));
            ulonglong2 l0 = __ldg(reinterpret_cast<const ulonglong2*>(pr + ro + xa));
            ulonglong2 l1 = __ldg(reinterpret_cast<const ulonglong2*>(pr + ro + xb));
            ulonglong2 l2 = __ldg(reinterpret_cast<const ulonglong2*>(pr + ro + xc));
            u64 vp[6] = { l0.x, l0.y, l1.x, l1.y, l2.x, l2.y };
#pragma unroll
            for (int dx = 0; dx < 5; ++dx) {
                u64 t0 = fma2_(vp[dx],     M1, cc.x);   // neighbor - center
                u64 t1 = fma2_(vp[dx + 1], M1, cc.y);
                d2[dx][0] = fma2_(t0, t0, d2[dx][0]);
                d2[dx][1] = fma2_(t1, t1, d2[dx][1]);
            }
        }

        // ---- raw weights for this dy (ephemeral, 10 u64) ----
        u64 w[5][2];
        const u64 mrow = pack2_(mr, mr);
#pragma unroll
        for (int dx = 0; dx < 5; ++dx) {
            float2 a = unpack2_(d2[dx][0]);
            float2 c = unpack2_(d2[dx][1]);
            u64 e0 = mul2_(pack2_(__expf(-a.x), __expf(-a.y)), mul2_(mX[dx][0], mrow));
            u64 e1 = mul2_(pack2_(__expf(-c.x), __expf(-c.y)), mul2_(mX[dx][1], mrow));
            w[dx][0] = e0;
            w[dx][1] = e1;
            ws0 = add2_(ws0, e0);
            ws1 = add2_(ws1, e1);
        }

        // ---- 24-channel accumulate: loads independent of weight math,
        //      24 independent acc chains ----
#pragma unroll
        for (int ch = 0; ch < COUT; ++ch) {
            const float* ir = inpb + ch * HWSZ + ro;
            ulonglong2 l0 = __ldg(reinterpret_cast<const ulonglong2*>(ir + xa));
            ulonglong2 l1 = __ldg(reinterpret_cast<const ulonglong2*>(ir + xb));
            ulonglong2 l2 = __ldg(reinterpret_cast<const ulonglong2*>(ir + xc));
            u64 vp[6] = { l0.x, l0.y, l1.x, l1.y, l2.x, l2.y };
#pragma unroll
            for (int dx = 0; dx < 5; ++dx) {
                acc[ch][0] = fma2_(w[dx][0], vp[dx],     acc[ch][0]);
                acc[ch][1] = fma2_(w[dx][1], vp[dx + 1], acc[ch][1]);
            }
        }
    }

    // ---- normalize once at the store ----
    float2 s0 = unpack2_(ws0), s1 = unpack2_(ws1);
    const u64 r0 = pack2_(__fdividef(1.0f, s0.x + 1e-8f),
                          __fdividef(1.0f, s0.y + 1e-8f));
    const u64 r1 = pack2_(__fdividef(1.0f, s1.x + 1e-8f),
                          __fdividef(1.0f, s1.y + 1e-8f));

#pragma unroll
    for (int ch = 0; ch < COUT; ++ch) {
        float2 f0 = unpack2_(mul2_(acc[ch][0], r0));
        float2 f1 = unpack2_(mul2_(acc[ch][1], r1));
        *reinterpret_cast<float4*>(outb + ch * HWSZ + cbase) =
            make_float4(f0.x, f0.y, f1.x, f1.y);
    }
}

extern "C" void kernel_launch(void* const* d_in, const int* in_sizes, int n_in,
                              void* d_out, int out_size)
{
    const float* inp = (const float*)d_in[0];   // (4,32,512,512) f32
    const float* par = (const float*)d_in[1];   // (4, 8,512,512) f32
    if (n_in >= 2 && in_sizes[0] < in_sizes[1]) {
        const float* t = inp; inp = par; par = t;
    }
    float* out = (float*)d_out;                 // (4,24,512,512) f32

    dim3 grid(WW / 128, HH / 4, 4);
    dim3 block(128);
    bilat_kernel<<<grid, block>>>(inp, par, out);
}

// round 6
// speedup vs baseline: 1.7458x; 1.7458x over previous
#include <cuda_runtime.h>

#define HH   512
#define WW   512
#define HWSZ (HH * WW)
#define CIN  32
#define COUT 24
#define NP   8

typedef unsigned long long u64;

// ---- B300 packed-f32 helpers (PTX f32x2 ops -> FFMA2 in SASS) ----
__device__ __forceinline__ u64 fma2_(u64 a, u64 b, u64 c) {
    u64 d; asm("fma.rn.f32x2 %0, %1, %2, %3;" : "=l"(d) : "l"(a), "l"(b), "l"(c)); return d;
}
__device__ __forceinline__ u64 add2_(u64 a, u64 b) {
    u64 d; asm("add.rn.f32x2 %0, %1, %2;" : "=l"(d) : "l"(a), "l"(b)); return d;
}
__device__ __forceinline__ u64 mul2_(u64 a, u64 b) {
    u64 d; asm("mul.rn.f32x2 %0, %1, %2;" : "=l"(d) : "l"(a), "l"(b)); return d;
}
__device__ __forceinline__ u64 pack2_(float lo, float hi) {
    u64 r; asm("mov.b64 %0, {%1, %2};" : "=l"(r) : "f"(lo), "f"(hi)); return r;
}
__device__ __forceinline__ float2 unpack2_(u64 v) {
    float lo, hi; asm("mov.b64 {%0, %1}, %2;" : "=f"(lo), "=f"(hi) : "l"(v));
    return make_float2(lo, hi);
}

// Single fused pass, dy loop FULLY UNROLLED into one flat body so ptxas can
// (a) overlap dy+1's param loads with dy's channel FMAs, (b) CSE the
// dy-invariant center-param loads. No min-blocks cap: registers are the MLP
// budget (R5 proved the 168-reg/3-CTA config starves in-flight loads).
__global__ void __launch_bounds__(128) bilat_kernel(
    const float* __restrict__ inp, const float* __restrict__ par,
    float* __restrict__ out)
{
    const int lane = threadIdx.x & 31;
    const int ty   = threadIdx.x >> 5;
    const int x0   = blockIdx.x * 128 + lane * 4;
    const int y    = blockIdx.y * 4 + ty;
    const int b    = blockIdx.z;

    const float* __restrict__ parb = par + b * (NP * HWSZ);
    const float* __restrict__ inpb = inp + b * (CIN * HWSZ);
    float* __restrict__ outb = out + b * (COUT * HWSZ);

    const int xa = max(x0 - 4, 0);          // clamped left col (16B aligned)
    const int xb = x0;
    const int xc = min(x0 + 4, WW - 4);     // clamped right col

    const int cbase = y * WW + x0;
    const u64 M1 = 0xBF800000BF800000ull;   // (-1.0f, -1.0f)

    // x-direction OOB masks (branch-free, computed once)
    u64 mX[5][2];
#pragma unroll
    for (int dx = 0; dx < 5; ++dx) {
        const int g = x0 + dx * 2 - 4;      // global x of tap for pixel 0
        mX[dx][0] = pack2_(((unsigned)(g + 0) < (unsigned)WW) ? 1.0f : 0.0f,
                           ((unsigned)(g + 1) < (unsigned)WW) ? 1.0f : 0.0f);
        mX[dx][1] = pack2_(((unsigned)(g + 2) < (unsigned)WW) ? 1.0f : 0.0f,
                           ((unsigned)(g + 3) < (unsigned)WW) ? 1.0f : 0.0f);
    }

    u64 acc[COUT][2];
#pragma unroll
    for (int c = 0; c < COUT; ++c) { acc[c][0] = 0ull; acc[c][1] = 0ull; }
    u64 ws0 = 0ull, ws1 = 0ull;

#pragma unroll
    for (int dy = 0; dy < 5; ++dy) {
        const int   ny = y + dy * 2 - 4;
        const float mr = ((unsigned)ny < (unsigned)HH) ? 1.0f : 0.0f;
        const int   ro = min(max(ny, 0), HH - 1) * WW;

        // ---- squared param distances: flat 32-load block ----
        u64 d2[5][2];
#pragma unroll
        for (int dx = 0; dx < 5; ++dx) { d2[dx][0] = 0ull; d2[dx][1] = 0ull; }

#pragma unroll
        for (int p = 0; p < NP; ++p) {
            const float* pr = parb + p * HWSZ;
            ulonglong2 cc = __ldg(reinterpret_cast<const ulonglong2*>(pr + cbase));
            ulonglong2 l0 = __ldg(reinterpret_cast<const ulonglong2*>(pr + ro + xa));
            ulonglong2 l1 = __ldg(reinterpret_cast<const ulonglong2*>(pr + ro + xb));
            ulonglong2 l2 = __ldg(reinterpret_cast<const ulonglong2*>(pr + ro + xc));
            u64 vp[6] = { l0.x, l0.y, l1.x, l1.y, l2.x, l2.y };
#pragma unroll
            for (int dx = 0; dx < 5; ++dx) {
                u64 t0 = fma2_(vp[dx],     M1, cc.x);   // neighbor - center
                u64 t1 = fma2_(vp[dx + 1], M1, cc.y);
                d2[dx][0] = fma2_(t0, t0, d2[dx][0]);
                d2[dx][1] = fma2_(t1, t1, d2[dx][1]);
            }
        }

        // ---- raw weights for this dy (ephemeral) ----
        u64 w[5][2];
        const u64 mrow = pack2_(mr, mr);
#pragma unroll
        for (int dx = 0; dx < 5; ++dx) {
            float2 a = unpack2_(d2[dx][0]);
            float2 c = unpack2_(d2[dx][1]);
            u64 e0 = mul2_(pack2_(__expf(-a.x), __expf(-a.y)), mul2_(mX[dx][0], mrow));
            u64 e1 = mul2_(pack2_(__expf(-c.x), __expf(-c.y)), mul2_(mX[dx][1], mrow));
            w[dx][0] = e0;
            w[dx][1] = e1;
            ws0 = add2_(ws0, e0);
            ws1 = add2_(ws1, e1);
        }

        // ---- 24-channel accumulate: loads independent of weight math,
        //      24 independent acc chains ----
#pragma unroll
        for (int ch = 0; ch < COUT; ++ch) {
            const float* ir = inpb + ch * HWSZ + ro;
            ulonglong2 l0 = __ldg(reinterpret_cast<const ulonglong2*>(ir + xa));
            ulonglong2 l1 = __ldg(reinterpret_cast<const ulonglong2*>(ir + xb));
            ulonglong2 l2 = __ldg(reinterpret_cast<const ulonglong2*>(ir + xc));
            u64 vp[6] = { l0.x, l0.y, l1.x, l1.y, l2.x, l2.y };
#pragma unroll
            for (int dx = 0; dx < 5; ++dx) {
                acc[ch][0] = fma2_(w[dx][0], vp[dx],     acc[ch][0]);
                acc[ch][1] = fma2_(w[dx][1], vp[dx + 1], acc[ch][1]);
            }
        }
    }

    // ---- normalize once at the store ----
    float2 s0 = unpack2_(ws0), s1 = unpack2_(ws1);
    const u64 r0 = pack2_(__fdividef(1.0f, s0.x + 1e-8f),
                          __fdividef(1.0f, s0.y + 1e-8f));
    const u64 r1 = pack2_(__fdividef(1.0f, s1.x + 1e-8f),
                          __fdividef(1.0f, s1.y + 1e-8f));

#pragma unroll
    for (int ch = 0; ch < COUT; ++ch) {
        float2 f0 = unpack2_(mul2_(acc[ch][0], r0));
        float2 f1 = unpack2_(mul2_(acc[ch][1], r1));
        *reinterpret_cast<float4*>(outb + ch * HWSZ + cbase) =
            make_float4(f0.x, f0.y, f1.x, f1.y);
    }
}

extern "C" void kernel_launch(void* const* d_in, const int* in_sizes, int n_in,
                              void* d_out, int out_size)
{
    const float* inp = (const float*)d_in[0];   // (4,32,512,512) f32
    const float* par = (const float*)d_in[1];   // (4, 8,512,512) f32
    if (n_in >= 2 && in_sizes[0] < in_sizes[1]) {
        const float* t = inp; inp = par; par = t;
    }
    float* out = (float*)d_out;                 // (4,24,512,512) f32

    dim3 grid(WW / 128, HH / 4, 4);
    dim3 block(128);
    bilat_kernel<<<grid, block>>>(inp, par, out);
}